// round 6
// baseline (speedup 1.0000x reference)
#include <cuda_runtime.h>
#include <cuda_fp16.h>

#define NB 144          // persistent blocks (<= 148 SMs -> co-resident)
#define NT 1024
#define NWARP 32
#define BB 128
#define NN 2592
#define CC 16
#define LL 64
#define NPB 18          // n per block (144*18 = 2592)
#define NSMEMROW 50     // rows/warp in smem
#define NSPILL 22       // rows/warp in global spill

typedef unsigned long long ull;

// ---------------- device scratch ----------------
__device__ float2   g_spart[NB * BB * 32];           // per-block partial s
__device__ float2   g_vf[BB * 32];                   // v_j fp32
__device__ float    g_bfull[NN];                     // routing logits (global view)
__device__ float    g_nsq[(size_t)BB * NN];          // ||u_hat[b,n,:]||^2
__device__ __half2  g_uspill[(size_t)NB * NWARP * NSPILL * 32]; // ~13MB spill rows
__device__ unsigned g_barrier;

// smem layout (bytes)
#define SM_U     0            // u rows: 32 warps * 50 rows * 128B = 204800
#define SM_XV    204800       // 16KB: x staging (ull[2048]) / v_sm (half2[4096])
#define SM_C     221184       // c_sm[18]
#define SM_BSL   221312       // b_slice[18]
#define SM_ARED  221440       // a_red[18*33]
#define SM_RED   223872       // red[32]
#define SM_GPAR  224128       // gmax, ginv
#define SMEM_TOTAL 224256

__global__ void k_init() { if (threadIdx.x == 0) g_barrier = 0u; }

__device__ __forceinline__ void gridsync(unsigned target) {
    __syncthreads();
    if (threadIdx.x == 0) {
        __threadfence();
        atomicAdd(&g_barrier, 1u);
        while (atomicAdd(&g_barrier, 0u) < target) __nanosleep(64);
        __threadfence();
    }
    __syncthreads();
}

__device__ __forceinline__ ull f22ull(float x, float y) {
    ull v; asm("mov.b64 %0, {%1,%2};" : "=l"(v) : "f"(x), "f"(y)); return v;
}
__device__ __forceinline__ float2 ull2f2(ull v) {
    float2 r; asm("mov.b64 {%0,%1}, %2;" : "=f"(r.x), "=f"(r.y) : "l"(v)); return r;
}
__device__ __forceinline__ void ffma2(ull& d, ull a, ull b) {
    asm("fma.rn.f32x2 %0, %1, %2, %0;" : "+l"(d) : "l"(a), "l"(b));
}
__device__ __forceinline__ float squash1(float s) {
    float sq = s * s;
    return sq * s / ((1.0f + sq) * sqrtf(sq));
}

__global__ __launch_bounds__(NT, 1) void cap_kernel(
    const float* __restrict__ x, const float* __restrict__ W,
    const float* __restrict__ conv_w, const float* __restrict__ conv_b,
    float* __restrict__ out)
{
    extern __shared__ unsigned char sm[];
    __half2* u_sm  = (__half2*)(sm + SM_U);
    ull*     x2_sm = (ull*)(sm + SM_XV);
    __half2* v_sm  = (__half2*)(sm + SM_XV);
    float*   c_sm  = (float*)(sm + SM_C);
    float*   b_sl  = (float*)(sm + SM_BSL);
    float*   a_red = (float*)(sm + SM_ARED);
    float*   red   = (float*)(sm + SM_RED);
    float*   gpar  = (float*)(sm + SM_GPAR);

    const int tid  = threadIdx.x;
    const int lane = tid & 31;
    const int w    = tid >> 5;
    const int blk  = blockIdx.x;
    const int nbase = blk * NPB;
    const int b0   = w * 4;

    if (tid < NPB) { b_sl[tid] = 0.0f; c_sm[tid] = 1.0f / (float)NN; }

    // x element this thread stages each iteration: (b, c) fixed, n varies
    const int xb = tid >> 4, xc = tid & 15;          // covers e = tid
    const int xb2 = (tid + NT) >> 4, xc2 = (tid + NT) & 15;

    // ================= producer: u_hat slice + norms (x prefetched) =================
    float pf0 = x[(size_t)xb  * (NN * CC) + (size_t)nbase * CC + xc];
    float pf1 = x[(size_t)xb2 * (NN * CC) + (size_t)nbase * CC + xc2];
    for (int nl = 0; nl < NPB; nl++) {
        const int ng = nbase + nl;
        x2_sm[tid]      = f22ull(pf0, pf0);
        x2_sm[tid + NT] = f22ull(pf1, pf1);
        __syncthreads();
        if (nl + 1 < NPB) { // issue next slice's LDGs early; overlap with FFMA block
            pf0 = x[(size_t)xb  * (NN * CC) + (size_t)(ng + 1) * CC + xc];
            pf1 = x[(size_t)xb2 * (NN * CC) + (size_t)(ng + 1) * CC + xc2];
        }

        const float4* Wg = (const float4*)(W + (size_t)ng * (LL * CC));
        const int l0 = lane * 2;
        ull acc[4];
        acc[0] = acc[1] = acc[2] = acc[3] = f22ull(0.f, 0.f);
#pragma unroll
        for (int h = 0; h < 2; h++) {
            float4 A0 = Wg[l0 * 4 + 2 * h];
            float4 B0 = Wg[(l0 + 1) * 4 + 2 * h];
            float4 A1 = Wg[l0 * 4 + 2 * h + 1];
            float4 B1 = Wg[(l0 + 1) * 4 + 2 * h + 1];
            ull wp[8];
            wp[0] = f22ull(A0.x, B0.x); wp[1] = f22ull(A0.y, B0.y);
            wp[2] = f22ull(A0.z, B0.z); wp[3] = f22ull(A0.w, B0.w);
            wp[4] = f22ull(A1.x, B1.x); wp[5] = f22ull(A1.y, B1.y);
            wp[6] = f22ull(A1.z, B1.z); wp[7] = f22ull(A1.w, B1.w);
#pragma unroll
            for (int j = 0; j < 4; j++) {
                const ull* xv = &x2_sm[(b0 + j) * 16 + 8 * h];
#pragma unroll
                for (int c = 0; c < 8; c++) ffma2(acc[j], wp[c], xv[c]);
            }
        }
#pragma unroll
        for (int j = 0; j < 4; j++) {
            float2 a = ull2f2(acc[j]);
            __half2 hv = __floats2half2_rn(a.x, a.y);
            int idx = j * NPB + nl;
            if (idx < NSMEMROW)
                u_sm[(w * NSMEMROW + idx) * 32 + lane] = hv;
            else
                g_uspill[(((size_t)blk * NWARP + w) * NSPILL + (idx - NSMEMROW)) * 32 + lane] = hv;
            float p = a.x * a.x + a.y * a.y;
#pragma unroll
            for (int o = 16; o; o >>= 1) p += __shfl_xor_sync(0xffffffffu, p, o);
            if (lane == 0) g_nsq[(size_t)(b0 + j) * NN + ng] = p;
        }
        __syncthreads();
    }

    // ================= routing iterations =================
    unsigned tgt = 0;
#pragma unroll 1
    for (int it = 0; it < 3; it++) {
        // ---- s-phase: partial s over this block's 18 n ----
        float2 sacc[4] = {{0.f,0.f},{0.f,0.f},{0.f,0.f},{0.f,0.f}};
        for (int nl = 0; nl < NPB; nl++) {
            float cn = c_sm[nl];
#pragma unroll
            for (int j = 0; j < 4; j++) {
                int idx = j * NPB + nl;
                __half2 hv = (idx < NSMEMROW)
                    ? u_sm[(w * NSMEMROW + idx) * 32 + lane]
                    : g_uspill[(((size_t)blk * NWARP + w) * NSPILL + (idx - NSMEMROW)) * 32 + lane];
                float2 u = __half22float2(hv);
                sacc[j].x += cn * u.x;
                sacc[j].y += cn * u.y;
            }
        }
#pragma unroll
        for (int j = 0; j < 4; j++)
            g_spart[(blk * BB + b0 + j) * 32 + lane] = sacc[j];
        tgt += NB; gridsync(tgt);

        // ---- stage2: reduce partials over blocks, squash -> v ----
        {
            int e = blk * 29 + w;
            if (w < 29 && e < BB * 32) {
                float2 s = {0.f, 0.f};
#pragma unroll
                for (int k = 0; k < 5; k++) {
                    int pp = lane + k * 32;
                    if (pp < NB) {
                        float2 t = g_spart[pp * (BB * 32) + e];
                        s.x += t.x; s.y += t.y;
                    }
                }
#pragma unroll
                for (int o = 16; o; o >>= 1) {
                    s.x += __shfl_xor_sync(0xffffffffu, s.x, o);
                    s.y += __shfl_xor_sync(0xffffffffu, s.y, o);
                }
                if (lane == 0) {
                    float2 v;
                    v.x = squash1(s.x);
                    v.y = squash1(s.y);
                    g_vf[e] = v;
                    if (it == 2) ((float2*)out)[e] = v;  // v_j output
                }
            }
        }
        if (it == 2) break;
        tgt += NB; gridsync(tgt);

        // ---- a-phase: v (fp16 in smem), dot with rows, update logits ----
#pragma unroll
        for (int r4 = 0; r4 < 4; r4++) {
            int e = tid + r4 * NT;
            float2 v = g_vf[e];
            v_sm[e] = __floats2half2_rn(v.x, v.y);
        }
        __syncthreads();
        for (int nl = 0; nl < NPB; nl++) {
            float a = 0.f;
#pragma unroll
            for (int j = 0; j < 4; j++) {
                int idx = j * NPB + nl;
                __half2 hv = (idx < NSMEMROW)
                    ? u_sm[(w * NSMEMROW + idx) * 32 + lane]
                    : g_uspill[(((size_t)blk * NWARP + w) * NSPILL + (idx - NSMEMROW)) * 32 + lane];
                float2 u = __half22float2(hv);
                float2 v = __half22float2(v_sm[(b0 + j) * 32 + lane]);
                a += u.x * v.x + u.y * v.y;
            }
#pragma unroll
            for (int o = 16; o; o >>= 1) a += __shfl_xor_sync(0xffffffffu, a, o);
            if (lane == 0) a_red[nl * 33 + w] = a;
        }
        __syncthreads();
        if (tid < NPB) {
            float s = 0.f;
#pragma unroll
            for (int k = 0; k < 32; k++) s += a_red[tid * 33 + k];
            float bn = b_sl[tid] + s * (1.0f / (float)BB);
            b_sl[tid] = bn;
            g_bfull[nbase + tid] = bn;
        }
        tgt += NB; gridsync(tgt);

        // ---- redundant per-block softmax over all 2592 logits ----
        {
            float l0v = g_bfull[tid];
            float l1v = g_bfull[tid + 1024];
            float l2v = (tid + 2048 < NN) ? g_bfull[tid + 2048] : -1e30f;
            float m = fmaxf(fmaxf(l0v, l1v), l2v);
#pragma unroll
            for (int o = 16; o; o >>= 1) m = fmaxf(m, __shfl_xor_sync(0xffffffffu, m, o));
            if (lane == 0) red[w] = m;
            __syncthreads();
            if (tid == 0) {
                float mm = red[0];
#pragma unroll
                for (int k = 1; k < 32; k++) mm = fmaxf(mm, red[k]);
                gpar[0] = mm;
            }
            __syncthreads();
            float gmax = gpar[0];
            float s = __expf(l0v - gmax) + __expf(l1v - gmax)
                    + ((tid + 2048 < NN) ? __expf(l2v - gmax) : 0.f);
#pragma unroll
            for (int o = 16; o; o >>= 1) s += __shfl_xor_sync(0xffffffffu, s, o);
            __syncthreads();
            if (lane == 0) red[w] = s;
            __syncthreads();
            if (tid == 0) {
                float t = 0.f;
#pragma unroll
                for (int k = 0; k < 32; k++) t += red[k];
                gpar[1] = 1.0f / t;
            }
            __syncthreads();
            float ginv = gpar[1];
            if (tid < NPB) c_sm[tid] = __expf(b_sl[tid] - gmax) * ginv;
            __syncthreads();
        }
    }

    // ================= conv transpose (blocks 0..127, b = blk) =================
    if (blk < BB) {
        float* sU = (float*)(sm);                 // [2592]
        float* sW = (float*)(sm + 10368);         // [4*64*32]
        float* sB = (float*)(sm + 10368 + 32768); // [64]
        const float gmax = gpar[0], ginv = gpar[1];
        __syncthreads();  // all warps done with u_sm before overwrite
        for (int i = tid; i < NN; i += NT)
            sU[i] = __expf(g_bfull[i] - gmax) * ginv * sqrtf(g_nsq[(size_t)blk * NN + i]);
        for (int i = tid; i < 8192; i += NT) {
            int kk = i >> 11, oc = (i >> 5) & 63, ic = i & 31;
            sW[i] = conv_w[(ic * 64 + oc) * 4 + kk];
        }
        if (tid < 64) sB[tid] = conv_b[tid];
        __syncthreads();
        if (tid < 256) {
            const int cw = tid >> 5;
            const int cl = tid & 31;
            const int kk = cw & 3;
            const int ky = kk >> 1, kx = kk & 1;
            const int half = cw >> 2;
            const int r = half * 4 + (cl >> 3);
            const int s = cl & 7;
            const int oy = 2 * r + (ky ? 0 : 1);
            const int ox = 2 * s + (kx ? 0 : 1);
            const int iy = r + (ky ? 0 : 1);
            const int ix = s + (kx ? 0 : 1);
            float u[32];
#pragma unroll
            for (int ic = 0; ic < 32; ic++) u[ic] = sU[ic * 81 + iy * 9 + ix];
            const float4* sW4 = (const float4*)(&sW[kk * 2048]);
            float* ob = out + BB * LL + (size_t)blk * 64 * 256 + oy * 16 + ox;
#pragma unroll 4
            for (int oc = 0; oc < 64; oc++) {
                float acc = sB[oc];
#pragma unroll
                for (int q = 0; q < 8; q++) {
                    float4 wv = sW4[oc * 8 + q];
                    acc += wv.x * u[4*q] + wv.y * u[4*q+1] + wv.z * u[4*q+2] + wv.w * u[4*q+3];
                }
                ob[oc * 256] = acc;
            }
        }
    }
}

// ---------------- launch ----------------
extern "C" void kernel_launch(void* const* d_in, const int* in_sizes, int n_in,
                              void* d_out, int out_size) {
    const float* x  = (const float*)d_in[0];
    const float* W  = (const float*)d_in[1];
    const float* cw = (const float*)d_in[2];
    const float* cb = (const float*)d_in[3];
    float* out = (float*)d_out;

    cudaFuncSetAttribute(cap_kernel, cudaFuncAttributeMaxDynamicSharedMemorySize, SMEM_TOTAL);
    k_init<<<1, 32>>>();
    cap_kernel<<<NB, NT, SMEM_TOTAL>>>(x, W, cw, cb, out);
}